// round 14
// baseline (speedup 1.0000x reference)
#include <cuda_runtime.h>
#include <cuda_fp16.h>
#include <math.h>
#include <cstdint>

#define NTOK 8192      // B*S
#define DIM  1024      // d_model
#define NE   8         // experts
#define TOPK 2
#define HID  4096      // expert hidden
#define NA   (NTOK*TOPK)   // 16384 assignments
#define CAP  NA            // per-expert bucket capacity (worst case)

// ---------------- device scratch (no allocations allowed) ----------------
__device__ int    g_bucket[NE*CAP];
__device__ int    g_cursor[NE];
__device__ float  g_prob_sum[NE];
__device__ float  g_topk_w[NA];
__device__ __half g_xh[(size_t)NTOK*DIM];         // fp16 x, 16.8 MB
__device__ __half g_wuh[(size_t)NE*DIM*HID];      // fp16 w_up  [e][k][n] (native), 67 MB
__device__ __half g_wdh[(size_t)NE*HID*DIM];      // fp16 w_down[e][k][n] (native), 67 MB
__device__ __half g_hh[(size_t)NA*HID];           // fp16 activations, 134 MB

// ---------------- kernel 1: cvt x to fp16 + zero output + zero counters ---
__global__ __launch_bounds__(256) void cvt_x_kernel(const float4* __restrict__ src, int n4,
                                                    float4* __restrict__ out_y, int o4) {
    if (blockIdx.x == 0 && threadIdx.x < NE) {
        g_cursor[threadIdx.x] = 0;
        g_prob_sum[threadIdx.x] = 0.f;
    }
    int stride = gridDim.x * blockDim.x;
    int idx0 = blockIdx.x * blockDim.x + threadIdx.x;
    for (int i = idx0; i < n4; i += stride) {
        float4 v = src[i];
        __half2 h01 = __floats2half2_rn(v.x, v.y);
        __half2 h23 = __floats2half2_rn(v.z, v.w);
        ((uint2*)g_xh)[i] = make_uint2(*(uint32_t*)&h01, *(uint32_t*)&h23);
    }
    float4 z = make_float4(0.f, 0.f, 0.f, 0.f);
    for (int i = idx0; i < o4; i += stride)
        out_y[i] = z;
}

// ---------------- kernel 2: straight fp32->fp16 cvt of both weights -------
__global__ __launch_bounds__(256) void cvt_w_kernel(
    const float4* __restrict__ wu, const float4* __restrict__ wd, int n4each)
{
    int stride = gridDim.x * blockDim.x;
    for (int i = blockIdx.x * blockDim.x + threadIdx.x; i < 2 * n4each; i += stride) {
        bool up = i < n4each;
        int j = up ? i : i - n4each;
        float4 v = up ? wu[j] : wd[j];
        __half2 h01 = __floats2half2_rn(v.x, v.y);
        __half2 h23 = __floats2half2_rn(v.z, v.w);
        uint2 p = make_uint2(*(uint32_t*)&h01, *(uint32_t*)&h23);
        if (up) ((uint2*)g_wuh)[j] = p;
        else    ((uint2*)g_wdh)[j] = p;
    }
}

// ---------------- kernel 3: router ----------------
__global__ __launch_bounds__(256) void router_kernel(
    const float* __restrict__ x, const float* __restrict__ rw,
    const float* __restrict__ rb, float* __restrict__ probs_out)
{
    int t   = blockIdx.x;
    int tid = threadIdx.x;
    const float* xr = x + (size_t)t * DIM;

    float acc[NE];
    #pragma unroll
    for (int e = 0; e < NE; e++) acc[e] = 0.f;

    for (int d = tid; d < DIM; d += 256) {
        float xv = xr[d];
        const float* w = rw + (size_t)d * NE;
        #pragma unroll
        for (int e = 0; e < NE; e++) acc[e] += xv * w[e];
    }
    #pragma unroll
    for (int e = 0; e < NE; e++) {
        #pragma unroll
        for (int off = 16; off > 0; off >>= 1)
            acc[e] += __shfl_down_sync(0xffffffffu, acc[e], off);
    }
    __shared__ float wsum[8][NE];
    int warp = tid >> 5, lane = tid & 31;
    if (lane == 0) {
        #pragma unroll
        for (int e = 0; e < NE; e++) wsum[warp][e] = acc[e];
    }
    __syncthreads();

    if (tid == 0) {
        float lg[NE];
        #pragma unroll
        for (int e = 0; e < NE; e++) {
            float s = rb[e];
            #pragma unroll
            for (int w = 0; w < 8; w++) s += wsum[w][e];
            lg[e] = s;
        }
        float mx = lg[0];
        #pragma unroll
        for (int e = 1; e < NE; e++) mx = fmaxf(mx, lg[e]);
        float p[NE], den = 0.f;
        #pragma unroll
        for (int e = 0; e < NE; e++) { p[e] = expf(lg[e] - mx); den += p[e]; }
        float inv = 1.f / den;
        #pragma unroll
        for (int e = 0; e < NE; e++) {
            p[e] *= inv;
            probs_out[(size_t)t * NE + e] = p[e];
            atomicAdd(&g_prob_sum[e], p[e]);
        }
        int i0 = 0;
        #pragma unroll
        for (int e = 1; e < NE; e++) if (lg[e] > lg[i0]) i0 = e;
        int i1 = -1;
        #pragma unroll
        for (int e = 0; e < NE; e++)
            if (e != i0 && (i1 < 0 || lg[e] > lg[i1])) i1 = e;
        float e1 = expf(lg[i1] - lg[i0]);
        float p0 = 1.f / (1.f + e1);
        float p1 = e1 * p0;

        int a0 = t * TOPK + 0, a1 = t * TOPK + 1;
        g_topk_w[a0] = p0;
        g_topk_w[a1] = p1;
        int s0 = atomicAdd(&g_cursor[i0], 1);
        g_bucket[i0 * CAP + s0] = a0;
        int s1 = atomicAdd(&g_cursor[i1], 1);
        g_bucket[i1 * CAP + s1] = a1;
    }
}

// ---------------- kernel: aux loss ----------------
__global__ void aux_kernel(float* __restrict__ out_aux) {
    if (threadIdx.x == 0) {
        float s = 0.f;
        #pragma unroll
        for (int e = 0; e < NE; e++)
            s += ((float)g_cursor[e] / (float)NA) * (g_prob_sum[e] / (float)NTOK);
        *out_aux = (float)NE * s * 0.01f;
    }
}

// ---------------- fp16 tensor-core grouped GEMM ----------------
// CTA tile 128x256, 256 threads, 8 warps in a 2x4 grid of 64x64 warp tiles
// (8 LDSM per 32 mma: crossbar demand ~33% below tensor demand).
// A tiles row-major [TM][72] (ldmatrix), B tiles K-MAJOR [TKK][264]
// (ldmatrix.trans, weights in native layout). 1 CTA/SM, 153 KB smem.
#define TM 128
#define TN 256
#define TKK 64
#define STAGES 3
#define A_STRIDE 72     // fp16/row (144B)
#define B_STRIDE 264    // fp16/row (528B); stride word 132 % 32 == 4 -> LDSM conflict-free
#define A_TILE_H (TM*A_STRIDE)     // 9216 halfs
#define B_TILE_H (TKK*B_STRIDE)    // 16896 halfs
#define SMEM_BYTES (STAGES*(A_TILE_H+B_TILE_H)*2 + TM*4)

__device__ __forceinline__ float gelu_tanh(float v) {
    float c = v * v * v;
    return 0.5f * v * (1.f + tanhf(0.7978845608028654f * (v + 0.044715f * c)));
}

__device__ __forceinline__ void mma_f16(float* c, const uint32_t* a, const uint32_t* b) {
    asm volatile(
        "mma.sync.aligned.m16n8k16.row.col.f32.f16.f16.f32 "
        "{%0,%1,%2,%3}, {%4,%5,%6,%7}, {%8,%9}, {%0,%1,%2,%3};"
        : "+f"(c[0]), "+f"(c[1]), "+f"(c[2]), "+f"(c[3])
        : "r"(a[0]), "r"(a[1]), "r"(a[2]), "r"(a[3]), "r"(b[0]), "r"(b[1]));
}

__device__ __forceinline__ void ldsm_x4(uint32_t& r0, uint32_t& r1, uint32_t& r2, uint32_t& r3,
                                        uint32_t addr) {
    asm volatile("ldmatrix.sync.aligned.m8n8.x4.shared.b16 {%0,%1,%2,%3}, [%4];"
                 : "=r"(r0), "=r"(r1), "=r"(r2), "=r"(r3) : "r"(addr));
}

__device__ __forceinline__ void ldsm_x4_trans(uint32_t& r0, uint32_t& r1, uint32_t& r2, uint32_t& r3,
                                              uint32_t addr) {
    asm volatile("ldmatrix.sync.aligned.m8n8.x4.trans.shared.b16 {%0,%1,%2,%3}, [%4];"
                 : "=r"(r0), "=r"(r1), "=r"(r2), "=r"(r3) : "r"(addr));
}

__device__ __forceinline__ void cp_async16(void* dst, const void* src, bool pred) {
    uint32_t d = (uint32_t)__cvta_generic_to_shared(dst);
    int sz = pred ? 16 : 0;
    asm volatile("cp.async.cg.shared.global [%0], [%1], 16, %2;\n"
                 :: "r"(d), "l"(src), "r"(sz));
}

// UP:  A = gathered g_xh rows, B = g_wuh[e] [DIM][HID], epilogue = gelu -> g_hh (fp16)
// DN:  A = gathered g_hh rows, B = g_wdh[e] [HID][DIM], epilogue = atomicAdd(w*(acc+bias)) -> out
template<bool UP>
__global__ __launch_bounds__(256, 1)
void mma_gemm_kernel(const float* __restrict__ Ball, float* __restrict__ out_y)
{
    constexpr int KD = UP ? DIM : HID;
    constexpr int ND = UP ? HID : DIM;
    constexpr int KT = KD / TKK;

    int e   = blockIdx.z;
    int cnt = g_cursor[e];
    int m0  = blockIdx.y * TM;
    if (m0 >= cnt) return;
    int n0  = blockIdx.x * TN;

    extern __shared__ __half smem[];
    __half* As = smem;                              // [STAGES][TM][A_STRIDE]
    __half* Bs = smem + STAGES * A_TILE_H;          // [STAGES][TKK][B_STRIDE]
    int*   rows = (int*)(Bs + STAGES * B_TILE_H);

    int tid = threadIdx.x;
    if (tid < TM) {
        int m = m0 + tid;
        rows[tid] = (m < cnt) ? g_bucket[e * CAP + m] : -1;
    }
    __syncthreads();

    const __half* W = (UP ? g_wuh : g_wdh) + (size_t)e * (size_t)KD * ND;
    const __half* Abase = UP ? (const __half*)g_xh : (const __half*)g_hh;

    auto issue = [&](int kt, int stage) {
        __half* as = As + stage * A_TILE_H;
        __half* bs = Bs + stage * B_TILE_H;
        int kbase = kt * TKK;
        #pragma unroll
        for (int i = 0; i < 4; i++) {          // A: 128 rows x 8 chunks of 16B
            int c = tid + i * 256;
            int r = c >> 3, q = c & 7;
            int a = rows[r];
            bool pred = (a >= 0);
            const __half* src = Abase +
                (UP ? (size_t)(pred ? (a >> 1) : 0) * DIM
                    : (size_t)(pred ? a : 0) * HID) + kbase + q * 8;
            cp_async16(as + r * A_STRIDE + q * 8, src, pred);
        }
        #pragma unroll
        for (int i = 0; i < 8; i++) {          // B: 64 k-rows x 32 chunks (n contiguous)
            int c = tid + i * 256;
            int k = c >> 5, q = c & 31;
            cp_async16(bs + k * B_STRIDE + q * 8,
                       W + (size_t)(kbase + k) * ND + n0 + q * 8, true);
        }
    };

    #pragma unroll
    for (int s = 0; s < STAGES - 1; s++) {
        if (s < KT) issue(s, s);
        asm volatile("cp.async.commit_group;");
    }

    int wid = tid >> 5, lane = tid & 31;
    int g = lane >> 2, t = lane & 3;
    int wm = (wid >> 2) * 64;   // 2x4 warp grid, 64x64 warp tiles
    int wn = (wid & 3) * 64;

    int sub = lane >> 3, r8 = lane & 7;
    // A (row-major): m0: rows wm..+7 k0 | m1: rows+8 k0 | m2: rows k8 | m3: rows+8 k8
    int a_off = (wm + (sub & 1) * 8 + r8) * A_STRIDE + (sub >> 1) * 8;
    // B (k-major, trans): m0: k0-7 col0 | m1: k8-15 col0 | m2: k0-7 col8 | m3: k8-15 col8
    int b_off = ((sub & 1) * 8 + r8) * B_STRIDE + wn + (sub >> 1) * 8;

    float acc[4][8][4];
    #pragma unroll
    for (int i = 0; i < 4; i++)
        #pragma unroll
        for (int j = 0; j < 8; j++)
            #pragma unroll
            for (int q = 0; q < 4; q++) acc[i][j][q] = 0.f;

    for (int kt = 0; kt < KT; kt++) {
        asm volatile("cp.async.wait_group %0;" :: "n"(STAGES - 2));
        __syncthreads();

        int nstage = kt + STAGES - 1;
        if (nstage < KT) issue(nstage, nstage % STAGES);
        asm volatile("cp.async.commit_group;");

        int st = kt % STAGES;
        uint32_t as_base = (uint32_t)__cvta_generic_to_shared(As + st * A_TILE_H) + a_off * 2;
        uint32_t bs_base = (uint32_t)__cvta_generic_to_shared(Bs + st * B_TILE_H) + b_off * 2;

        uint32_t af[4][4];      // A fragments for current ks (64 rows)
        uint32_t bf[2][2][2];   // B pair double-buffer: [buf][jj][reg]

        // prologue: B pair (ks=0, jp=0)
        ldsm_x4_trans(bf[0][0][0], bf[0][0][1], bf[0][1][0], bf[0][1][1], bs_base);

        #pragma unroll
        for (int ks = 0; ks < TKK / 16; ks++) {
            #pragma unroll
            for (int i = 0; i < 4; i++)
                ldsm_x4(af[i][0], af[i][1], af[i][2], af[i][3],
                        as_base + (i * 16 * A_STRIDE + ks * 16) * 2);
            #pragma unroll
            for (int jp = 0; jp < 4; jp++) {
                int cur = jp & 1, nxt = cur ^ 1;
                bool more = (jp < 3) || (ks < TKK / 16 - 1);
                int njp = (jp < 3) ? jp + 1 : 0;
                int nks = (jp < 3) ? ks : ks + 1;
                if (more)
                    ldsm_x4_trans(bf[nxt][0][0], bf[nxt][0][1], bf[nxt][1][0], bf[nxt][1][1],
                                  bs_base + (nks * 16 * B_STRIDE + njp * 16) * 2);
                #pragma unroll
                for (int i = 0; i < 4; i++) {
                    mma_f16(acc[i][2*jp    ], af[i], bf[cur][0]);
                    mma_f16(acc[i][2*jp + 1], af[i], bf[cur][1]);
                }
            }
        }
    }

    // epilogue
    const float* bb = Ball + (size_t)e * ND + n0;
    #pragma unroll
    for (int i = 0; i < 4; i++) {
        int r0 = wm + i * 16 + g;
        int r1 = r0 + 8;
        int a0 = rows[r0], a1 = rows[r1];
        if (UP) {
            #pragma unroll
            for (int j = 0; j < 8; j++) {
                int col = wn + j * 8 + t * 2;
                float bx = bb[col], by = bb[col + 1];
                if (a0 >= 0) {
                    float v0 = gelu_tanh(acc[i][j][0] + bx);
                    float v1 = gelu_tanh(acc[i][j][1] + by);
                    *(__half2*)(g_hh + (size_t)a0 * HID + n0 + col) = __floats2half2_rn(v0, v1);
                }
                if (a1 >= 0) {
                    float v2 = gelu_tanh(acc[i][j][2] + bx);
                    float v3 = gelu_tanh(acc[i][j][3] + by);
                    *(__half2*)(g_hh + (size_t)a1 * HID + n0 + col) = __floats2half2_rn(v2, v3);
                }
            }
        } else {
            float w0 = (a0 >= 0) ? g_topk_w[a0] : 0.f;
            float w1 = (a1 >= 0) ? g_topk_w[a1] : 0.f;
            float* o0 = out_y + (size_t)(a0 >> 1) * DIM + n0;
            float* o1 = out_y + (size_t)(a1 >> 1) * DIM + n0;
            #pragma unroll
            for (int j = 0; j < 8; j++) {
                int col = wn + j * 8 + t * 2;
                float bx = bb[col], by = bb[col + 1];
                if (a0 >= 0) {
                    atomicAdd(o0 + col,     w0 * (acc[i][j][0] + bx));
                    atomicAdd(o0 + col + 1, w0 * (acc[i][j][1] + by));
                }
                if (a1 >= 0) {
                    atomicAdd(o1 + col,     w1 * (acc[i][j][2] + bx));
                    atomicAdd(o1 + col + 1, w1 * (acc[i][j][3] + by));
                }
            }
        }
    }
}

// ---------------- launch ----------------
extern "C" void kernel_launch(void* const* d_in, const int* in_sizes, int n_in,
                              void* d_out, int out_size)
{
    const float* x  = (const float*)d_in[0];
    const float* rw = (const float*)d_in[1];
    const float* rb = (const float*)d_in[2];
    const float* wu = (const float*)d_in[3];
    const float* bu = (const float*)d_in[4];
    const float* wd = (const float*)d_in[5];
    const float* bd = (const float*)d_in[6];

    float* out       = (float*)d_out;
    float* out_y     = out;
    float* out_aux   = out + (size_t)NTOK * DIM;
    float* out_probs = out_aux + 1;

    cudaFuncSetAttribute(mma_gemm_kernel<true>,
        cudaFuncAttributeMaxDynamicSharedMemorySize, SMEM_BYTES);
    cudaFuncSetAttribute(mma_gemm_kernel<false>,
        cudaFuncAttributeMaxDynamicSharedMemorySize, SMEM_BYTES);

    // launch order keeps the up-GEMM at position 4 (ncu captures launch #4)
    cvt_x_kernel<<<1184, 256>>>((const float4*)x, NTOK * DIM / 4,
                                (float4*)out_y, NTOK * DIM / 4);          // 1
    cvt_w_kernel<<<2368, 256>>>((const float4*)wu, (const float4*)wd,
                                NE * DIM * HID / 4);                      // 2
    router_kernel<<<NTOK, 256>>>(x, rw, rb, out_probs);                   // 3

    dim3 gu(HID / TN, CAP / TM, NE);
    mma_gemm_kernel<true><<<gu, 256, SMEM_BYTES>>>(bu, out_y);            // 4 <- profiled

    aux_kernel<<<1, 32>>>(out_aux);                                       // 5

    dim3 gd(DIM / TN, CAP / TM, NE);
    mma_gemm_kernel<false><<<gd, 256, SMEM_BYTES>>>(bd, out_y);           // 6
}

// round 15
// speedup vs baseline: 1.0555x; 1.0555x over previous
#include <cuda_runtime.h>
#include <cuda_fp16.h>
#include <math.h>
#include <cstdint>

#define NTOK 8192      // B*S
#define DIM  1024      // d_model
#define NE   8         // experts
#define TOPK 2
#define HID  4096      // expert hidden
#define NA   (NTOK*TOPK)   // 16384 assignments
#define CAP  NA            // per-expert bucket capacity (worst case)
#define MTILES 16          // persistent m-tile stride (grid.y)

// ---------------- device scratch (no allocations allowed) ----------------
__device__ int    g_bucket[NE*CAP];
__device__ int    g_cursor[NE];
__device__ float  g_prob_sum[NE];
__device__ float  g_topk_w[NA];
__device__ __half g_xh[(size_t)NTOK*DIM];         // fp16 x, 16.8 MB
__device__ __half g_wuh[(size_t)NE*DIM*HID];      // fp16 w_up  [e][k][n] (native), 67 MB
__device__ __half g_wdh[(size_t)NE*HID*DIM];      // fp16 w_down[e][k][n] (native), 67 MB
__device__ __half g_hh[(size_t)NA*HID];           // fp16 activations, 134 MB

// ---------------- kernel 1: fused cvt x + zero out + cvt both weights -----
// flat grid over: [0, XN4) x-convert, [XN4, XN4+O4) zero out, then weights.
#define XN4 (NTOK*DIM/4)
#define WN4 (NE*DIM*HID/4)
__global__ __launch_bounds__(256) void cvt_all_kernel(
    const float4* __restrict__ x, const float4* __restrict__ wu,
    const float4* __restrict__ wd, float4* __restrict__ out_y)
{
    if (blockIdx.x == 0 && threadIdx.x < NE) {
        g_cursor[threadIdx.x] = 0;
        g_prob_sum[threadIdx.x] = 0.f;
    }
    int stride = gridDim.x * blockDim.x;
    int total = XN4 + XN4 + 2 * WN4;   // x, zero, wu, wd
    for (int i = blockIdx.x * blockDim.x + threadIdx.x; i < total; i += stride) {
        if (i < XN4) {
            float4 v = x[i];
            __half2 h01 = __floats2half2_rn(v.x, v.y);
            __half2 h23 = __floats2half2_rn(v.z, v.w);
            ((uint2*)g_xh)[i] = make_uint2(*(uint32_t*)&h01, *(uint32_t*)&h23);
        } else if (i < 2 * XN4) {
            out_y[i - XN4] = make_float4(0.f, 0.f, 0.f, 0.f);
        } else {
            int j = i - 2 * XN4;
            bool up = j < WN4;
            int k = up ? j : j - WN4;
            float4 v = up ? wu[k] : wd[k];
            __half2 h01 = __floats2half2_rn(v.x, v.y);
            __half2 h23 = __floats2half2_rn(v.z, v.w);
            uint2 p = make_uint2(*(uint32_t*)&h01, *(uint32_t*)&h23);
            if (up) ((uint2*)g_wuh)[k] = p;
            else    ((uint2*)g_wdh)[k] = p;
        }
    }
}

// ---------------- kernel 2: router ----------------
__global__ __launch_bounds__(256) void router_kernel(
    const float* __restrict__ x, const float* __restrict__ rw,
    const float* __restrict__ rb, float* __restrict__ probs_out)
{
    int t   = blockIdx.x;
    int tid = threadIdx.x;
    const float* xr = x + (size_t)t * DIM;

    float acc[NE];
    #pragma unroll
    for (int e = 0; e < NE; e++) acc[e] = 0.f;

    for (int d = tid; d < DIM; d += 256) {
        float xv = xr[d];
        const float* w = rw + (size_t)d * NE;
        #pragma unroll
        for (int e = 0; e < NE; e++) acc[e] += xv * w[e];
    }
    #pragma unroll
    for (int e = 0; e < NE; e++) {
        #pragma unroll
        for (int off = 16; off > 0; off >>= 1)
            acc[e] += __shfl_down_sync(0xffffffffu, acc[e], off);
    }
    __shared__ float wsum[8][NE];
    int warp = tid >> 5, lane = tid & 31;
    if (lane == 0) {
        #pragma unroll
        for (int e = 0; e < NE; e++) wsum[warp][e] = acc[e];
    }
    __syncthreads();

    if (tid == 0) {
        float lg[NE];
        #pragma unroll
        for (int e = 0; e < NE; e++) {
            float s = rb[e];
            #pragma unroll
            for (int w = 0; w < 8; w++) s += wsum[w][e];
            lg[e] = s;
        }
        float mx = lg[0];
        #pragma unroll
        for (int e = 1; e < NE; e++) mx = fmaxf(mx, lg[e]);
        float p[NE], den = 0.f;
        #pragma unroll
        for (int e = 0; e < NE; e++) { p[e] = expf(lg[e] - mx); den += p[e]; }
        float inv = 1.f / den;
        #pragma unroll
        for (int e = 0; e < NE; e++) {
            p[e] *= inv;
            probs_out[(size_t)t * NE + e] = p[e];
            atomicAdd(&g_prob_sum[e], p[e]);
        }
        int i0 = 0;
        #pragma unroll
        for (int e = 1; e < NE; e++) if (lg[e] > lg[i0]) i0 = e;
        int i1 = -1;
        #pragma unroll
        for (int e = 0; e < NE; e++)
            if (e != i0 && (i1 < 0 || lg[e] > lg[i1])) i1 = e;
        float e1 = expf(lg[i1] - lg[i0]);
        float p0 = 1.f / (1.f + e1);
        float p1 = e1 * p0;

        int a0 = t * TOPK + 0, a1 = t * TOPK + 1;
        g_topk_w[a0] = p0;
        g_topk_w[a1] = p1;
        int s0 = atomicAdd(&g_cursor[i0], 1);
        g_bucket[i0 * CAP + s0] = a0;
        int s1 = atomicAdd(&g_cursor[i1], 1);
        g_bucket[i1 * CAP + s1] = a1;
    }
}

// ---------------- kernel 3: aux loss ----------------
__global__ void aux_kernel(float* __restrict__ out_aux) {
    if (threadIdx.x == 0) {
        float s = 0.f;
        #pragma unroll
        for (int e = 0; e < NE; e++)
            s += ((float)g_cursor[e] / (float)NA) * (g_prob_sum[e] / (float)NTOK);
        *out_aux = (float)NE * s * 0.01f;
    }
}

// ---------------- fp16 tensor-core grouped GEMM (R12 config) --------------
// 256 threads, 8 warps (4x2 grid of 32x64 warp tiles), 2 CTAs/SM,
// m16n8k16 fp16 mma, ldmatrix (A) + ldmatrix.trans (B, k-major native
// weights), TKK=64, 3-stage cp.async, PERSISTENT over m-tiles (grid.y=16).
#define TM 128
#define TN 128
#define TKK 64
#define STAGES 3
#define A_STRIDE 72     // fp16/row (144B)
#define B_STRIDE 136    // fp16/row (272B); 8-row LDSM phase covers all 32 banks
#define A_TILE_H (TM*A_STRIDE)     // 9216 halfs
#define B_TILE_H (TKK*B_STRIDE)    // 8704 halfs
#define SMEM_BYTES (STAGES*(A_TILE_H+B_TILE_H)*2 + TM*4)

__device__ __forceinline__ float gelu_tanh(float v) {
    float c = v * v * v;
    return 0.5f * v * (1.f + tanhf(0.7978845608028654f * (v + 0.044715f * c)));
}

__device__ __forceinline__ void mma_f16(float* c, const uint32_t* a, const uint32_t* b) {
    asm volatile(
        "mma.sync.aligned.m16n8k16.row.col.f32.f16.f16.f32 "
        "{%0,%1,%2,%3}, {%4,%5,%6,%7}, {%8,%9}, {%0,%1,%2,%3};"
        : "+f"(c[0]), "+f"(c[1]), "+f"(c[2]), "+f"(c[3])
        : "r"(a[0]), "r"(a[1]), "r"(a[2]), "r"(a[3]), "r"(b[0]), "r"(b[1]));
}

__device__ __forceinline__ void ldsm_x4(uint32_t& r0, uint32_t& r1, uint32_t& r2, uint32_t& r3,
                                        uint32_t addr) {
    asm volatile("ldmatrix.sync.aligned.m8n8.x4.shared.b16 {%0,%1,%2,%3}, [%4];"
                 : "=r"(r0), "=r"(r1), "=r"(r2), "=r"(r3) : "r"(addr));
}

__device__ __forceinline__ void ldsm_x4_trans(uint32_t& r0, uint32_t& r1, uint32_t& r2, uint32_t& r3,
                                              uint32_t addr) {
    asm volatile("ldmatrix.sync.aligned.m8n8.x4.trans.shared.b16 {%0,%1,%2,%3}, [%4];"
                 : "=r"(r0), "=r"(r1), "=r"(r2), "=r"(r3) : "r"(addr));
}

__device__ __forceinline__ void cp_async16(void* dst, const void* src, bool pred) {
    uint32_t d = (uint32_t)__cvta_generic_to_shared(dst);
    int sz = pred ? 16 : 0;
    asm volatile("cp.async.cg.shared.global [%0], [%1], 16, %2;\n"
                 :: "r"(d), "l"(src), "r"(sz));
}

// UP:  A = gathered g_xh rows, B = g_wuh[e] [DIM][HID], epilogue = gelu -> g_hh (fp16)
// DN:  A = gathered g_hh rows, B = g_wdh[e] [HID][DIM], epilogue = atomicAdd(w*(acc+bias)) -> out
template<bool UP>
__global__ __launch_bounds__(256, 2)
void mma_gemm_kernel(const float* __restrict__ Ball, float* __restrict__ out_y)
{
    constexpr int KD = UP ? DIM : HID;
    constexpr int ND = UP ? HID : DIM;
    constexpr int KT = KD / TKK;

    int e   = blockIdx.z;
    int cnt = g_cursor[e];
    int n0  = blockIdx.x * TN;

    extern __shared__ __half smem[];
    __half* As = smem;                              // [STAGES][TM][A_STRIDE]
    __half* Bs = smem + STAGES * A_TILE_H;          // [STAGES][TKK][B_STRIDE]
    int*   rows = (int*)(Bs + STAGES * B_TILE_H);

    int tid = threadIdx.x;
    int wid = tid >> 5, lane = tid & 31;
    int g = lane >> 2, t = lane & 3;
    int wm = (wid >> 1) * 32;   // 4x2 warp grid, 32x64 warp tiles
    int wn = (wid & 1) * 64;

    int sub = lane >> 3, r8 = lane & 7;
    int a_off = (wm + (sub & 1) * 8 + r8) * A_STRIDE + (sub >> 1) * 8;
    int b_off = ((sub & 1) * 8 + r8) * B_STRIDE + wn + (sub >> 1) * 8;

    const __half* W = (UP ? g_wuh : g_wdh) + (size_t)e * (size_t)KD * ND;
    const __half* Abase = UP ? (const __half*)g_xh : (const __half*)g_hh;

    // persistent loop over m-tiles
    for (int m0 = blockIdx.y * TM; m0 < cnt; m0 += MTILES * TM) {

        if (tid < TM) {
            int m = m0 + tid;
            rows[tid] = (m < cnt) ? g_bucket[e * CAP + m] : -1;
        }
        __syncthreads();

        auto issue = [&](int kt, int stage) {
            __half* as = As + stage * A_TILE_H;
            __half* bs = Bs + stage * B_TILE_H;
            int kbase = kt * TKK;
            #pragma unroll
            for (int i = 0; i < 4; i++) {          // A: 128 rows x 8 chunks of 16B
                int c = tid + i * 256;
                int r = c >> 3, q = c & 7;
                int a = rows[r];
                bool pred = (a >= 0);
                const __half* src = Abase +
                    (UP ? (size_t)(pred ? (a >> 1) : 0) * DIM
                        : (size_t)(pred ? a : 0) * HID) + kbase + q * 8;
                cp_async16(as + r * A_STRIDE + q * 8, src, pred);
            }
            #pragma unroll
            for (int i = 0; i < 4; i++) {          // B: 64 k-rows x 16 chunks
                int c = tid + i * 256;
                int k = c >> 4, q = c & 15;
                cp_async16(bs + k * B_STRIDE + q * 8,
                           W + (size_t)(kbase + k) * ND + n0 + q * 8, true);
            }
        };

        #pragma unroll
        for (int s = 0; s < STAGES - 1; s++) {
            if (s < KT) issue(s, s);
            asm volatile("cp.async.commit_group;");
        }

        float acc[2][8][4];
        #pragma unroll
        for (int i = 0; i < 2; i++)
            #pragma unroll
            for (int j = 0; j < 8; j++)
                #pragma unroll
                for (int q = 0; q < 4; q++) acc[i][j][q] = 0.f;

        for (int kt = 0; kt < KT; kt++) {
            asm volatile("cp.async.wait_group %0;" :: "n"(STAGES - 2));
            __syncthreads();

            int nstage = kt + STAGES - 1;
            if (nstage < KT) issue(nstage, nstage % STAGES);
            asm volatile("cp.async.commit_group;");

            int st = kt % STAGES;
            uint32_t as_base = (uint32_t)__cvta_generic_to_shared(As + st * A_TILE_H) + a_off * 2;
            uint32_t bs_base = (uint32_t)__cvta_generic_to_shared(Bs + st * B_TILE_H) + b_off * 2;

            uint32_t af[2][4];      // A fragments for current ks
            uint32_t bf[2][2][2];   // B pair double-buffer

            ldsm_x4_trans(bf[0][0][0], bf[0][0][1], bf[0][1][0], bf[0][1][1], bs_base);

            #pragma unroll
            for (int ks = 0; ks < TKK / 16; ks++) {
                #pragma unroll
                for (int i = 0; i < 2; i++)
                    ldsm_x4(af[i][0], af[i][1], af[i][2], af[i][3],
                            as_base + (i * 16 * A_STRIDE + ks * 16) * 2);
                #pragma unroll
                for (int jp = 0; jp < 4; jp++) {
                    int cur = jp & 1, nxt = cur ^ 1;
                    bool more = (jp < 3) || (ks < TKK / 16 - 1);
                    int njp = (jp < 3) ? jp + 1 : 0;
                    int nks = (jp < 3) ? ks : ks + 1;
                    if (more)
                        ldsm_x4_trans(bf[nxt][0][0], bf[nxt][0][1], bf[nxt][1][0], bf[nxt][1][1],
                                      bs_base + (nks * 16 * B_STRIDE + njp * 16) * 2);
                    mma_f16(acc[0][2*jp    ], af[0], bf[cur][0]);
                    mma_f16(acc[0][2*jp + 1], af[0], bf[cur][1]);
                    mma_f16(acc[1][2*jp    ], af[1], bf[cur][0]);
                    mma_f16(acc[1][2*jp + 1], af[1], bf[cur][1]);
                }
            }
        }

        // epilogue
        const float* bb = Ball + (size_t)e * ND + n0;
        #pragma unroll
        for (int i = 0; i < 2; i++) {
            int r0 = wm + i * 16 + g;
            int r1 = r0 + 8;
            int a0 = rows[r0], a1 = rows[r1];
            if (UP) {
                #pragma unroll
                for (int j = 0; j < 8; j++) {
                    int col = wn + j * 8 + t * 2;
                    float bx = bb[col], by = bb[col + 1];
                    if (a0 >= 0) {
                        float v0 = gelu_tanh(acc[i][j][0] + bx);
                        float v1 = gelu_tanh(acc[i][j][1] + by);
                        *(__half2*)(g_hh + (size_t)a0 * HID + n0 + col) = __floats2half2_rn(v0, v1);
                    }
                    if (a1 >= 0) {
                        float v2 = gelu_tanh(acc[i][j][2] + bx);
                        float v3 = gelu_tanh(acc[i][j][3] + by);
                        *(__half2*)(g_hh + (size_t)a1 * HID + n0 + col) = __floats2half2_rn(v2, v3);
                    }
                }
            } else {
                float w0 = (a0 >= 0) ? g_topk_w[a0] : 0.f;
                float w1 = (a1 >= 0) ? g_topk_w[a1] : 0.f;
                float* o0 = out_y + (size_t)(a0 >> 1) * DIM + n0;
                float* o1 = out_y + (size_t)(a1 >> 1) * DIM + n0;
                #pragma unroll
                for (int j = 0; j < 8; j++) {
                    int col = wn + j * 8 + t * 2;
                    float bx = bb[col], by = bb[col + 1];
                    if (a0 >= 0) {
                        atomicAdd(o0 + col,     w0 * (acc[i][j][0] + bx));
                        atomicAdd(o0 + col + 1, w0 * (acc[i][j][1] + by));
                    }
                    if (a1 >= 0) {
                        atomicAdd(o1 + col,     w1 * (acc[i][j][2] + bx));
                        atomicAdd(o1 + col + 1, w1 * (acc[i][j][3] + by));
                    }
                }
            }
        }
        __syncthreads();   // protect rows[] before next m-tile overwrites it
    }
}

// ---------------- launch ----------------
extern "C" void kernel_launch(void* const* d_in, const int* in_sizes, int n_in,
                              void* d_out, int out_size)
{
    const float* x  = (const float*)d_in[0];
    const float* rw = (const float*)d_in[1];
    const float* rb = (const float*)d_in[2];
    const float* wu = (const float*)d_in[3];
    const float* bu = (const float*)d_in[4];
    const float* wd = (const float*)d_in[5];
    const float* bd = (const float*)d_in[6];

    float* out       = (float*)d_out;
    float* out_y     = out;
    float* out_aux   = out + (size_t)NTOK * DIM;
    float* out_probs = out_aux + 1;

    cudaFuncSetAttribute(mma_gemm_kernel<true>,
        cudaFuncAttributeMaxDynamicSharedMemorySize, SMEM_BYTES);
    cudaFuncSetAttribute(mma_gemm_kernel<false>,
        cudaFuncAttributeMaxDynamicSharedMemorySize, SMEM_BYTES);

    // launch order keeps the up-GEMM at position 4 (ncu captures launch #4)
    cvt_all_kernel<<<2368, 256>>>((const float4*)x, (const float4*)wu,
                                  (const float4*)wd, (float4*)out_y);     // 1
    router_kernel<<<NTOK, 256>>>(x, rw, rb, out_probs);                   // 2
    aux_kernel<<<1, 32>>>(out_aux);                                       // 3

    dim3 gu(HID / TN, MTILES, NE);
    mma_gemm_kernel<true><<<gu, 256, SMEM_BYTES>>>(bu, out_y);            // 4 <- profiled

    dim3 gd(DIM / TN, MTILES, NE);
    mma_gemm_kernel<false><<<gd, 256, SMEM_BYTES>>>(bd, out_y);           // 5
}

// round 16
// speedup vs baseline: 1.1745x; 1.1128x over previous
#include <cuda_runtime.h>
#include <cuda_fp16.h>
#include <math.h>
#include <cstdint>

#define NTOK 8192      // B*S
#define DIM  1024      // d_model
#define NE   8         // experts
#define TOPK 2
#define HID  4096      // expert hidden
#define NA   (NTOK*TOPK)   // 16384 assignments
#define CAP  NA            // per-expert bucket capacity (worst case)

// ---------------- device scratch (no allocations allowed) ----------------
__device__ int    g_bucket[NE*CAP];
__device__ int    g_cursor[NE];
__device__ float  g_prob_sum[NE];
__device__ float  g_topk_w[NA];
__device__ __half g_xh[(size_t)NTOK*DIM];         // fp16 x, 16.8 MB
__device__ __half g_wuh[(size_t)NE*DIM*HID];      // fp16 w_up  [e][k][n] (native), 67 MB
__device__ __half g_wdh[(size_t)NE*HID*DIM];      // fp16 w_down[e][k][n] (native), 67 MB
__device__ __half g_hh[(size_t)NA*HID];           // fp16 activations, 134 MB

#define XN4 (NTOK*DIM/4)
#define WN4 (NE*DIM*HID/4)

// ---------------- kernel 1: cvt x + zero out (branch-free, MLP=2) ---------
__global__ __launch_bounds__(256) void cvt_x_kernel(
    const float4* __restrict__ x, float4* __restrict__ out_y)
{
    if (blockIdx.x == 0 && threadIdx.x < NE) {
        g_cursor[threadIdx.x] = 0;
        g_prob_sum[threadIdx.x] = 0.f;
    }
    int stride = gridDim.x * blockDim.x;
    float4 z = make_float4(0.f, 0.f, 0.f, 0.f);
    for (int i = blockIdx.x * blockDim.x + threadIdx.x; i < XN4; i += stride) {
        float4 v = x[i];
        __half2 h01 = __floats2half2_rn(v.x, v.y);
        __half2 h23 = __floats2half2_rn(v.z, v.w);
        ((uint2*)g_xh)[i] = make_uint2(*(uint32_t*)&h01, *(uint32_t*)&h23);
        out_y[i] = z;
    }
}

// ---------------- kernel 2: cvt both weights (branch-free, MLP=2) ---------
__global__ __launch_bounds__(256) void cvt_w_kernel(
    const float4* __restrict__ wu, const float4* __restrict__ wd)
{
    int stride = gridDim.x * blockDim.x;
    for (int j = blockIdx.x * blockDim.x + threadIdx.x; j < WN4; j += stride) {
        float4 a = wu[j];
        float4 b = wd[j];
        __half2 a01 = __floats2half2_rn(a.x, a.y);
        __half2 a23 = __floats2half2_rn(a.z, a.w);
        __half2 b01 = __floats2half2_rn(b.x, b.y);
        __half2 b23 = __floats2half2_rn(b.z, b.w);
        ((uint2*)g_wuh)[j] = make_uint2(*(uint32_t*)&a01, *(uint32_t*)&a23);
        ((uint2*)g_wdh)[j] = make_uint2(*(uint32_t*)&b01, *(uint32_t*)&b23);
    }
}

// ---------------- kernel 3: router ----------------
__global__ __launch_bounds__(256) void router_kernel(
    const float* __restrict__ x, const float* __restrict__ rw,
    const float* __restrict__ rb, float* __restrict__ probs_out)
{
    int t   = blockIdx.x;
    int tid = threadIdx.x;
    const float* xr = x + (size_t)t * DIM;

    float acc[NE];
    #pragma unroll
    for (int e = 0; e < NE; e++) acc[e] = 0.f;

    for (int d = tid; d < DIM; d += 256) {
        float xv = xr[d];
        const float* w = rw + (size_t)d * NE;
        #pragma unroll
        for (int e = 0; e < NE; e++) acc[e] += xv * w[e];
    }
    #pragma unroll
    for (int e = 0; e < NE; e++) {
        #pragma unroll
        for (int off = 16; off > 0; off >>= 1)
            acc[e] += __shfl_down_sync(0xffffffffu, acc[e], off);
    }
    __shared__ float wsum[8][NE];
    int warp = tid >> 5, lane = tid & 31;
    if (lane == 0) {
        #pragma unroll
        for (int e = 0; e < NE; e++) wsum[warp][e] = acc[e];
    }
    __syncthreads();

    if (tid == 0) {
        float lg[NE];
        #pragma unroll
        for (int e = 0; e < NE; e++) {
            float s = rb[e];
            #pragma unroll
            for (int w = 0; w < 8; w++) s += wsum[w][e];
            lg[e] = s;
        }
        float mx = lg[0];
        #pragma unroll
        for (int e = 1; e < NE; e++) mx = fmaxf(mx, lg[e]);
        float p[NE], den = 0.f;
        #pragma unroll
        for (int e = 0; e < NE; e++) { p[e] = expf(lg[e] - mx); den += p[e]; }
        float inv = 1.f / den;
        #pragma unroll
        for (int e = 0; e < NE; e++) {
            p[e] *= inv;
            probs_out[(size_t)t * NE + e] = p[e];
            atomicAdd(&g_prob_sum[e], p[e]);
        }
        int i0 = 0;
        #pragma unroll
        for (int e = 1; e < NE; e++) if (lg[e] > lg[i0]) i0 = e;
        int i1 = -1;
        #pragma unroll
        for (int e = 0; e < NE; e++)
            if (e != i0 && (i1 < 0 || lg[e] > lg[i1])) i1 = e;
        float e1 = expf(lg[i1] - lg[i0]);
        float p0 = 1.f / (1.f + e1);
        float p1 = e1 * p0;

        int a0 = t * TOPK + 0, a1 = t * TOPK + 1;
        g_topk_w[a0] = p0;
        g_topk_w[a1] = p1;
        int s0 = atomicAdd(&g_cursor[i0], 1);
        g_bucket[i0 * CAP + s0] = a0;
        int s1 = atomicAdd(&g_cursor[i1], 1);
        g_bucket[i1 * CAP + s1] = a1;
    }
}

// ---------------- kernel: aux loss ----------------
__global__ void aux_kernel(float* __restrict__ out_aux) {
    if (threadIdx.x == 0) {
        float s = 0.f;
        #pragma unroll
        for (int e = 0; e < NE; e++)
            s += ((float)g_cursor[e] / (float)NA) * (g_prob_sum[e] / (float)NTOK);
        *out_aux = (float)NE * s * 0.01f;
    }
}

// ---------------- fp16 tensor-core grouped GEMM (R12 config, verbatim) ----
// 256 threads, 8 warps (4x2 grid of 32x64 warp tiles), 2 CTAs/SM,
// m16n8k16 fp16 mma, ldmatrix (A) + ldmatrix.trans (B, k-major native
// weights), TKK=64, 3-stage cp.async, early-exit dead m-tiles.
#define TM 128
#define TN 128
#define TKK 64
#define STAGES 3
#define A_STRIDE 72     // fp16/row (144B)
#define B_STRIDE 136    // fp16/row (272B); 8-row LDSM phase covers all 32 banks
#define A_TILE_H (TM*A_STRIDE)     // 9216 halfs
#define B_TILE_H (TKK*B_STRIDE)    // 8704 halfs
#define SMEM_BYTES (STAGES*(A_TILE_H+B_TILE_H)*2 + TM*4)

__device__ __forceinline__ float gelu_tanh(float v) {
    float c = v * v * v;
    return 0.5f * v * (1.f + tanhf(0.7978845608028654f * (v + 0.044715f * c)));
}

__device__ __forceinline__ void mma_f16(float* c, const uint32_t* a, const uint32_t* b) {
    asm volatile(
        "mma.sync.aligned.m16n8k16.row.col.f32.f16.f16.f32 "
        "{%0,%1,%2,%3}, {%4,%5,%6,%7}, {%8,%9}, {%0,%1,%2,%3};"
        : "+f"(c[0]), "+f"(c[1]), "+f"(c[2]), "+f"(c[3])
        : "r"(a[0]), "r"(a[1]), "r"(a[2]), "r"(a[3]), "r"(b[0]), "r"(b[1]));
}

__device__ __forceinline__ void ldsm_x4(uint32_t& r0, uint32_t& r1, uint32_t& r2, uint32_t& r3,
                                        uint32_t addr) {
    asm volatile("ldmatrix.sync.aligned.m8n8.x4.shared.b16 {%0,%1,%2,%3}, [%4];"
                 : "=r"(r0), "=r"(r1), "=r"(r2), "=r"(r3) : "r"(addr));
}

__device__ __forceinline__ void ldsm_x4_trans(uint32_t& r0, uint32_t& r1, uint32_t& r2, uint32_t& r3,
                                              uint32_t addr) {
    asm volatile("ldmatrix.sync.aligned.m8n8.x4.trans.shared.b16 {%0,%1,%2,%3}, [%4];"
                 : "=r"(r0), "=r"(r1), "=r"(r2), "=r"(r3) : "r"(addr));
}

__device__ __forceinline__ void cp_async16(void* dst, const void* src, bool pred) {
    uint32_t d = (uint32_t)__cvta_generic_to_shared(dst);
    int sz = pred ? 16 : 0;
    asm volatile("cp.async.cg.shared.global [%0], [%1], 16, %2;\n"
                 :: "r"(d), "l"(src), "r"(sz));
}

// UP:  A = gathered g_xh rows, B = g_wuh[e] [DIM][HID], epilogue = gelu -> g_hh (fp16)
// DN:  A = gathered g_hh rows, B = g_wdh[e] [HID][DIM], epilogue = atomicAdd(w*(acc+bias)) -> out
template<bool UP>
__global__ __launch_bounds__(256, 2)
void mma_gemm_kernel(const float* __restrict__ Ball, float* __restrict__ out_y)
{
    constexpr int KD = UP ? DIM : HID;
    constexpr int ND = UP ? HID : DIM;
    constexpr int KT = KD / TKK;

    int e   = blockIdx.z;
    int cnt = g_cursor[e];
    int m0  = blockIdx.y * TM;
    if (m0 >= cnt) return;
    int n0  = blockIdx.x * TN;

    extern __shared__ __half smem[];
    __half* As = smem;                              // [STAGES][TM][A_STRIDE]
    __half* Bs = smem + STAGES * A_TILE_H;          // [STAGES][TKK][B_STRIDE]
    int*   rows = (int*)(Bs + STAGES * B_TILE_H);

    int tid = threadIdx.x;
    if (tid < TM) {
        int m = m0 + tid;
        rows[tid] = (m < cnt) ? g_bucket[e * CAP + m] : -1;
    }
    __syncthreads();

    const __half* W = (UP ? g_wuh : g_wdh) + (size_t)e * (size_t)KD * ND;
    const __half* Abase = UP ? (const __half*)g_xh : (const __half*)g_hh;

    auto issue = [&](int kt, int stage) {
        __half* as = As + stage * A_TILE_H;
        __half* bs = Bs + stage * B_TILE_H;
        int kbase = kt * TKK;
        #pragma unroll
        for (int i = 0; i < 4; i++) {          // A: 128 rows x 8 chunks of 16B
            int c = tid + i * 256;
            int r = c >> 3, q = c & 7;
            int a = rows[r];
            bool pred = (a >= 0);
            const __half* src = Abase +
                (UP ? (size_t)(pred ? (a >> 1) : 0) * DIM
                    : (size_t)(pred ? a : 0) * HID) + kbase + q * 8;
            cp_async16(as + r * A_STRIDE + q * 8, src, pred);
        }
        #pragma unroll
        for (int i = 0; i < 4; i++) {          // B: 64 k-rows x 16 chunks (n contiguous)
            int c = tid + i * 256;
            int k = c >> 4, q = c & 15;
            cp_async16(bs + k * B_STRIDE + q * 8,
                       W + (size_t)(kbase + k) * ND + n0 + q * 8, true);
        }
    };

    #pragma unroll
    for (int s = 0; s < STAGES - 1; s++) {
        if (s < KT) issue(s, s);
        asm volatile("cp.async.commit_group;");
    }

    int wid = tid >> 5, lane = tid & 31;
    int g = lane >> 2, t = lane & 3;
    int wm = (wid >> 1) * 32;   // 4x2 warp grid, 32x64 warp tiles
    int wn = (wid & 1) * 64;

    int sub = lane >> 3, r8 = lane & 7;
    int a_off = (wm + (sub & 1) * 8 + r8) * A_STRIDE + (sub >> 1) * 8;
    int b_off = ((sub & 1) * 8 + r8) * B_STRIDE + wn + (sub >> 1) * 8;

    float acc[2][8][4];
    #pragma unroll
    for (int i = 0; i < 2; i++)
        #pragma unroll
        for (int j = 0; j < 8; j++)
            #pragma unroll
            for (int q = 0; q < 4; q++) acc[i][j][q] = 0.f;

    for (int kt = 0; kt < KT; kt++) {
        asm volatile("cp.async.wait_group %0;" :: "n"(STAGES - 2));
        __syncthreads();

        int nstage = kt + STAGES - 1;
        if (nstage < KT) issue(nstage, nstage % STAGES);
        asm volatile("cp.async.commit_group;");

        int st = kt % STAGES;
        uint32_t as_base = (uint32_t)__cvta_generic_to_shared(As + st * A_TILE_H) + a_off * 2;
        uint32_t bs_base = (uint32_t)__cvta_generic_to_shared(Bs + st * B_TILE_H) + b_off * 2;

        uint32_t af[2][4];      // A fragments for current ks
        uint32_t bf[2][2][2];   // B pair double-buffer: [buf][jj][reg]

        ldsm_x4_trans(bf[0][0][0], bf[0][0][1], bf[0][1][0], bf[0][1][1], bs_base);

        #pragma unroll
        for (int ks = 0; ks < TKK / 16; ks++) {
            #pragma unroll
            for (int i = 0; i < 2; i++)
                ldsm_x4(af[i][0], af[i][1], af[i][2], af[i][3],
                        as_base + (i * 16 * A_STRIDE + ks * 16) * 2);
            #pragma unroll
            for (int jp = 0; jp < 4; jp++) {
                int cur = jp & 1, nxt = cur ^ 1;
                bool more = (jp < 3) || (ks < TKK / 16 - 1);
                int njp = (jp < 3) ? jp + 1 : 0;
                int nks = (jp < 3) ? ks : ks + 1;
                if (more)
                    ldsm_x4_trans(bf[nxt][0][0], bf[nxt][0][1], bf[nxt][1][0], bf[nxt][1][1],
                                  bs_base + (nks * 16 * B_STRIDE + njp * 16) * 2);
                mma_f16(acc[0][2*jp    ], af[0], bf[cur][0]);
                mma_f16(acc[0][2*jp + 1], af[0], bf[cur][1]);
                mma_f16(acc[1][2*jp    ], af[1], bf[cur][0]);
                mma_f16(acc[1][2*jp + 1], af[1], bf[cur][1]);
            }
        }
    }

    // epilogue
    const float* bb = Ball + (size_t)e * ND + n0;
    #pragma unroll
    for (int i = 0; i < 2; i++) {
        int r0 = wm + i * 16 + g;
        int r1 = r0 + 8;
        int a0 = rows[r0], a1 = rows[r1];
        if (UP) {
            #pragma unroll
            for (int j = 0; j < 8; j++) {
                int col = wn + j * 8 + t * 2;
                float bx = bb[col], by = bb[col + 1];
                if (a0 >= 0) {
                    float v0 = gelu_tanh(acc[i][j][0] + bx);
                    float v1 = gelu_tanh(acc[i][j][1] + by);
                    *(__half2*)(g_hh + (size_t)a0 * HID + n0 + col) = __floats2half2_rn(v0, v1);
                }
                if (a1 >= 0) {
                    float v2 = gelu_tanh(acc[i][j][2] + bx);
                    float v3 = gelu_tanh(acc[i][j][3] + by);
                    *(__half2*)(g_hh + (size_t)a1 * HID + n0 + col) = __floats2half2_rn(v2, v3);
                }
            }
        } else {
            float w0 = (a0 >= 0) ? g_topk_w[a0] : 0.f;
            float w1 = (a1 >= 0) ? g_topk_w[a1] : 0.f;
            float* o0 = out_y + (size_t)(a0 >> 1) * DIM + n0;
            float* o1 = out_y + (size_t)(a1 >> 1) * DIM + n0;
            #pragma unroll
            for (int j = 0; j < 8; j++) {
                int col = wn + j * 8 + t * 2;
                float bx = bb[col], by = bb[col + 1];
                if (a0 >= 0) {
                    atomicAdd(o0 + col,     w0 * (acc[i][j][0] + bx));
                    atomicAdd(o0 + col + 1, w0 * (acc[i][j][1] + by));
                }
                if (a1 >= 0) {
                    atomicAdd(o1 + col,     w1 * (acc[i][j][2] + bx));
                    atomicAdd(o1 + col + 1, w1 * (acc[i][j][3] + by));
                }
            }
        }
    }
}

// ---------------- launch ----------------
extern "C" void kernel_launch(void* const* d_in, const int* in_sizes, int n_in,
                              void* d_out, int out_size)
{
    const float* x  = (const float*)d_in[0];
    const float* rw = (const float*)d_in[1];
    const float* rb = (const float*)d_in[2];
    const float* wu = (const float*)d_in[3];
    const float* bu = (const float*)d_in[4];
    const float* wd = (const float*)d_in[5];
    const float* bd = (const float*)d_in[6];

    float* out       = (float*)d_out;
    float* out_y     = out;
    float* out_aux   = out + (size_t)NTOK * DIM;
    float* out_probs = out_aux + 1;

    cudaFuncSetAttribute(mma_gemm_kernel<true>,
        cudaFuncAttributeMaxDynamicSharedMemorySize, SMEM_BYTES);
    cudaFuncSetAttribute(mma_gemm_kernel<false>,
        cudaFuncAttributeMaxDynamicSharedMemorySize, SMEM_BYTES);

    // launch order keeps the up-GEMM at position 4 (ncu captures launch #4)
    cvt_x_kernel<<<1184, 256>>>((const float4*)x, (float4*)out_y);        // 1
    cvt_w_kernel<<<2368, 256>>>((const float4*)wu, (const float4*)wd);    // 2
    router_kernel<<<NTOK, 256>>>(x, rw, rb, out_probs);                   // 3

    dim3 gu(HID / TN, CAP / TM, NE);
    mma_gemm_kernel<true><<<gu, 256, SMEM_BYTES>>>(bu, out_y);            // 4 <- profiled

    aux_kernel<<<1, 32>>>(out_aux);                                       // 5

    dim3 gd(DIM / TN, CAP / TM, NE);
    mma_gemm_kernel<false><<<gd, 256, SMEM_BYTES>>>(bd, out_y);           // 6
}

// round 17
// speedup vs baseline: 1.2135x; 1.0332x over previous
#include <cuda_runtime.h>
#include <cuda_fp16.h>
#include <math.h>
#include <cstdint>

#define NTOK 8192      // B*S
#define DIM  1024      // d_model
#define NE   8         // experts
#define TOPK 2
#define HID  4096      // expert hidden
#define NA   (NTOK*TOPK)   // 16384 assignments
#define CAP  NA            // per-expert bucket capacity (worst case)

// ---------------- device scratch (no allocations allowed) ----------------
__device__ int    g_bucket[NE*CAP];
__device__ int    g_cursor[NE];
__device__ float  g_prob_sum[NE];
__device__ float  g_topk_w[NA];
__device__ __half g_xh[(size_t)NTOK*DIM];         // fp16 x, 16.8 MB
__device__ __half g_wuh[(size_t)NE*DIM*HID];      // fp16 w_up  [e][k][n] (native), 67 MB
__device__ __half g_wdh[(size_t)NE*HID*DIM];      // fp16 w_down[e][k][n] (native), 67 MB
__device__ __half g_hh[(size_t)NA*HID];           // fp16 activations, 134 MB

#define WN4 (NE*DIM*HID/4)

// ---------------- kernel: zero counters ----------------
__global__ void zero_kernel() {
    int t = threadIdx.x;
    if (t < NE) { g_cursor[t] = 0; g_prob_sum[t] = 0.f; }
}

// ---------------- kernel: convert ONE weight tensor fp32->fp16 ------------
__global__ __launch_bounds__(256) void cvt_w1_kernel(
    const float4* __restrict__ w, uint2* __restrict__ dst)
{
    int stride = gridDim.x * blockDim.x;
    for (int j = blockIdx.x * blockDim.x + threadIdx.x; j < WN4; j += stride) {
        float4 v = w[j];
        __half2 h01 = __floats2half2_rn(v.x, v.y);
        __half2 h23 = __floats2half2_rn(v.z, v.w);
        dst[j] = make_uint2(*(uint32_t*)&h01, *(uint32_t*)&h23);
    }
}

// ---------------- kernel: router (+ fp16 x convert + output zero) ---------
__global__ __launch_bounds__(256) void router_kernel(
    const float* __restrict__ x, const float* __restrict__ rw,
    const float* __restrict__ rb, float* __restrict__ probs_out,
    float* __restrict__ out_y)
{
    int t   = blockIdx.x;
    int tid = threadIdx.x;
    const float* xr = x + (size_t)t * DIM;
    __half* xh = g_xh + (size_t)t * DIM;
    float*  oy = out_y + (size_t)t * DIM;

    float acc[NE];
    #pragma unroll
    for (int e = 0; e < NE; e++) acc[e] = 0.f;

    for (int d = tid; d < DIM; d += 256) {
        float xv = xr[d];
        xh[d] = __float2half(xv);    // fused x conversion
        oy[d] = 0.f;                 // fused output zero (pre-down atomics)
        const float* w = rw + (size_t)d * NE;
        #pragma unroll
        for (int e = 0; e < NE; e++) acc[e] += xv * w[e];
    }
    #pragma unroll
    for (int e = 0; e < NE; e++) {
        #pragma unroll
        for (int off = 16; off > 0; off >>= 1)
            acc[e] += __shfl_down_sync(0xffffffffu, acc[e], off);
    }
    __shared__ float wsum[8][NE];
    int warp = tid >> 5, lane = tid & 31;
    if (lane == 0) {
        #pragma unroll
        for (int e = 0; e < NE; e++) wsum[warp][e] = acc[e];
    }
    __syncthreads();

    if (tid == 0) {
        float lg[NE];
        #pragma unroll
        for (int e = 0; e < NE; e++) {
            float s = rb[e];
            #pragma unroll
            for (int w = 0; w < 8; w++) s += wsum[w][e];
            lg[e] = s;
        }
        float mx = lg[0];
        #pragma unroll
        for (int e = 1; e < NE; e++) mx = fmaxf(mx, lg[e]);
        float p[NE], den = 0.f;
        #pragma unroll
        for (int e = 0; e < NE; e++) { p[e] = expf(lg[e] - mx); den += p[e]; }
        float inv = 1.f / den;
        #pragma unroll
        for (int e = 0; e < NE; e++) {
            p[e] *= inv;
            probs_out[(size_t)t * NE + e] = p[e];
            atomicAdd(&g_prob_sum[e], p[e]);
        }
        int i0 = 0;
        #pragma unroll
        for (int e = 1; e < NE; e++) if (lg[e] > lg[i0]) i0 = e;
        int i1 = -1;
        #pragma unroll
        for (int e = 0; e < NE; e++)
            if (e != i0 && (i1 < 0 || lg[e] > lg[i1])) i1 = e;
        float e1 = expf(lg[i1] - lg[i0]);
        float p0 = 1.f / (1.f + e1);
        float p1 = e1 * p0;

        int a0 = t * TOPK + 0, a1 = t * TOPK + 1;
        g_topk_w[a0] = p0;
        g_topk_w[a1] = p1;
        int s0 = atomicAdd(&g_cursor[i0], 1);
        g_bucket[i0 * CAP + s0] = a0;
        int s1 = atomicAdd(&g_cursor[i1], 1);
        g_bucket[i1 * CAP + s1] = a1;
    }
}

// ---------------- kernel: aux loss ----------------
__global__ void aux_kernel(float* __restrict__ out_aux) {
    if (threadIdx.x == 0) {
        float s = 0.f;
        #pragma unroll
        for (int e = 0; e < NE; e++)
            s += ((float)g_cursor[e] / (float)NA) * (g_prob_sum[e] / (float)NTOK);
        *out_aux = (float)NE * s * 0.01f;
    }
}

// ---------------- fp16 tensor-core grouped GEMM (R12/R16 config) ----------
// 256 threads, 8 warps (4x2 grid of 32x64 warp tiles), 2 CTAs/SM,
// m16n8k16 fp16 mma, ldmatrix (A) + ldmatrix.trans (B, k-major native
// weights), TKK=64, 3-stage cp.async, early-exit dead m-tiles.
#define TM 128
#define TN 128
#define TKK 64
#define STAGES 3
#define A_STRIDE 72     // fp16/row (144B)
#define B_STRIDE 136    // fp16/row (272B); 8-row LDSM phase covers all 32 banks
#define A_TILE_H (TM*A_STRIDE)     // 9216 halfs
#define B_TILE_H (TKK*B_STRIDE)    // 8704 halfs
#define SMEM_BYTES (STAGES*(A_TILE_H+B_TILE_H)*2 + TM*4)

__device__ __forceinline__ float gelu_tanh(float v) {
    float c = v * v * v;
    return 0.5f * v * (1.f + tanhf(0.7978845608028654f * (v + 0.044715f * c)));
}

__device__ __forceinline__ void mma_f16(float* c, const uint32_t* a, const uint32_t* b) {
    asm volatile(
        "mma.sync.aligned.m16n8k16.row.col.f32.f16.f16.f32 "
        "{%0,%1,%2,%3}, {%4,%5,%6,%7}, {%8,%9}, {%0,%1,%2,%3};"
        : "+f"(c[0]), "+f"(c[1]), "+f"(c[2]), "+f"(c[3])
        : "r"(a[0]), "r"(a[1]), "r"(a[2]), "r"(a[3]), "r"(b[0]), "r"(b[1]));
}

__device__ __forceinline__ void ldsm_x4(uint32_t& r0, uint32_t& r1, uint32_t& r2, uint32_t& r3,
                                        uint32_t addr) {
    asm volatile("ldmatrix.sync.aligned.m8n8.x4.shared.b16 {%0,%1,%2,%3}, [%4];"
                 : "=r"(r0), "=r"(r1), "=r"(r2), "=r"(r3) : "r"(addr));
}

__device__ __forceinline__ void ldsm_x4_trans(uint32_t& r0, uint32_t& r1, uint32_t& r2, uint32_t& r3,
                                              uint32_t addr) {
    asm volatile("ldmatrix.sync.aligned.m8n8.x4.trans.shared.b16 {%0,%1,%2,%3}, [%4];"
                 : "=r"(r0), "=r"(r1), "=r"(r2), "=r"(r3) : "r"(addr));
}

__device__ __forceinline__ void cp_async16(void* dst, const void* src, bool pred) {
    uint32_t d = (uint32_t)__cvta_generic_to_shared(dst);
    int sz = pred ? 16 : 0;
    asm volatile("cp.async.cg.shared.global [%0], [%1], 16, %2;\n"
                 :: "r"(d), "l"(src), "r"(sz));
}

// UP:  A = gathered g_xh rows, B = g_wuh[e] [DIM][HID], epilogue = gelu -> g_hh (fp16)
// DN:  A = gathered g_hh rows, B = g_wdh[e] [HID][DIM], epilogue = atomicAdd(w*(acc+bias)) -> out
template<bool UP>
__global__ __launch_bounds__(256, 2)
void mma_gemm_kernel(const float* __restrict__ Ball, float* __restrict__ out_y)
{
    constexpr int KD = UP ? DIM : HID;
    constexpr int ND = UP ? HID : DIM;
    constexpr int KT = KD / TKK;

    int e   = blockIdx.z;
    int cnt = g_cursor[e];
    int m0  = blockIdx.y * TM;
    if (m0 >= cnt) return;
    int n0  = blockIdx.x * TN;

    extern __shared__ __half smem[];
    __half* As = smem;                              // [STAGES][TM][A_STRIDE]
    __half* Bs = smem + STAGES * A_TILE_H;          // [STAGES][TKK][B_STRIDE]
    int*   rows = (int*)(Bs + STAGES * B_TILE_H);

    int tid = threadIdx.x;
    if (tid < TM) {
        int m = m0 + tid;
        rows[tid] = (m < cnt) ? g_bucket[e * CAP + m] : -1;
    }
    __syncthreads();

    const __half* W = (UP ? g_wuh : g_wdh) + (size_t)e * (size_t)KD * ND;
    const __half* Abase = UP ? (const __half*)g_xh : (const __half*)g_hh;

    auto issue = [&](int kt, int stage) {
        __half* as = As + stage * A_TILE_H;
        __half* bs = Bs + stage * B_TILE_H;
        int kbase = kt * TKK;
        #pragma unroll
        for (int i = 0; i < 4; i++) {          // A: 128 rows x 8 chunks of 16B
            int c = tid + i * 256;
            int r = c >> 3, q = c & 7;
            int a = rows[r];
            bool pred = (a >= 0);
            const __half* src = Abase +
                (UP ? (size_t)(pred ? (a >> 1) : 0) * DIM
                    : (size_t)(pred ? a : 0) * HID) + kbase + q * 8;
            cp_async16(as + r * A_STRIDE + q * 8, src, pred);
        }
        #pragma unroll
        for (int i = 0; i < 4; i++) {          // B: 64 k-rows x 16 chunks (n contiguous)
            int c = tid + i * 256;
            int k = c >> 4, q = c & 15;
            cp_async16(bs + k * B_STRIDE + q * 8,
                       W + (size_t)(kbase + k) * ND + n0 + q * 8, true);
        }
    };

    #pragma unroll
    for (int s = 0; s < STAGES - 1; s++) {
        if (s < KT) issue(s, s);
        asm volatile("cp.async.commit_group;");
    }

    int wid = tid >> 5, lane = tid & 31;
    int g = lane >> 2, t = lane & 3;
    int wm = (wid >> 1) * 32;   // 4x2 warp grid, 32x64 warp tiles
    int wn = (wid & 1) * 64;

    int sub = lane >> 3, r8 = lane & 7;
    int a_off = (wm + (sub & 1) * 8 + r8) * A_STRIDE + (sub >> 1) * 8;
    int b_off = ((sub & 1) * 8 + r8) * B_STRIDE + wn + (sub >> 1) * 8;

    float acc[2][8][4];
    #pragma unroll
    for (int i = 0; i < 2; i++)
        #pragma unroll
        for (int j = 0; j < 8; j++)
            #pragma unroll
            for (int q = 0; q < 4; q++) acc[i][j][q] = 0.f;

    for (int kt = 0; kt < KT; kt++) {
        asm volatile("cp.async.wait_group %0;" :: "n"(STAGES - 2));
        __syncthreads();

        int nstage = kt + STAGES - 1;
        if (nstage < KT) issue(nstage, nstage % STAGES);
        asm volatile("cp.async.commit_group;");

        int st = kt % STAGES;
        uint32_t as_base = (uint32_t)__cvta_generic_to_shared(As + st * A_TILE_H) + a_off * 2;
        uint32_t bs_base = (uint32_t)__cvta_generic_to_shared(Bs + st * B_TILE_H) + b_off * 2;

        uint32_t af[2][4];      // A fragments for current ks
        uint32_t bf[2][2][2];   // B pair double-buffer: [buf][jj][reg]

        ldsm_x4_trans(bf[0][0][0], bf[0][0][1], bf[0][1][0], bf[0][1][1], bs_base);

        #pragma unroll
        for (int ks = 0; ks < TKK / 16; ks++) {
            #pragma unroll
            for (int i = 0; i < 2; i++)
                ldsm_x4(af[i][0], af[i][1], af[i][2], af[i][3],
                        as_base + (i * 16 * A_STRIDE + ks * 16) * 2);
            #pragma unroll
            for (int jp = 0; jp < 4; jp++) {
                int cur = jp & 1, nxt = cur ^ 1;
                bool more = (jp < 3) || (ks < TKK / 16 - 1);
                int njp = (jp < 3) ? jp + 1 : 0;
                int nks = (jp < 3) ? ks : ks + 1;
                if (more)
                    ldsm_x4_trans(bf[nxt][0][0], bf[nxt][0][1], bf[nxt][1][0], bf[nxt][1][1],
                                  bs_base + (nks * 16 * B_STRIDE + njp * 16) * 2);
                mma_f16(acc[0][2*jp    ], af[0], bf[cur][0]);
                mma_f16(acc[0][2*jp + 1], af[0], bf[cur][1]);
                mma_f16(acc[1][2*jp    ], af[1], bf[cur][0]);
                mma_f16(acc[1][2*jp + 1], af[1], bf[cur][1]);
            }
        }
    }

    // epilogue
    const float* bb = Ball + (size_t)e * ND + n0;
    #pragma unroll
    for (int i = 0; i < 2; i++) {
        int r0 = wm + i * 16 + g;
        int r1 = r0 + 8;
        int a0 = rows[r0], a1 = rows[r1];
        if (UP) {
            #pragma unroll
            for (int j = 0; j < 8; j++) {
                int col = wn + j * 8 + t * 2;
                float bx = bb[col], by = bb[col + 1];
                if (a0 >= 0) {
                    float v0 = gelu_tanh(acc[i][j][0] + bx);
                    float v1 = gelu_tanh(acc[i][j][1] + by);
                    *(__half2*)(g_hh + (size_t)a0 * HID + n0 + col) = __floats2half2_rn(v0, v1);
                }
                if (a1 >= 0) {
                    float v2 = gelu_tanh(acc[i][j][2] + bx);
                    float v3 = gelu_tanh(acc[i][j][3] + by);
                    *(__half2*)(g_hh + (size_t)a1 * HID + n0 + col) = __floats2half2_rn(v2, v3);
                }
            }
        } else {
            float w0 = (a0 >= 0) ? g_topk_w[a0] : 0.f;
            float w1 = (a1 >= 0) ? g_topk_w[a1] : 0.f;
            float* o0 = out_y + (size_t)(a0 >> 1) * DIM + n0;
            float* o1 = out_y + (size_t)(a1 >> 1) * DIM + n0;
            #pragma unroll
            for (int j = 0; j < 8; j++) {
                int col = wn + j * 8 + t * 2;
                float bx = bb[col], by = bb[col + 1];
                if (a0 >= 0) {
                    atomicAdd(o0 + col,     w0 * (acc[i][j][0] + bx));
                    atomicAdd(o0 + col + 1, w0 * (acc[i][j][1] + by));
                }
                if (a1 >= 0) {
                    atomicAdd(o1 + col,     w1 * (acc[i][j][2] + bx));
                    atomicAdd(o1 + col + 1, w1 * (acc[i][j][3] + by));
                }
            }
        }
    }
}

// ---------------- launch ----------------
extern "C" void kernel_launch(void* const* d_in, const int* in_sizes, int n_in,
                              void* d_out, int out_size)
{
    const float* x  = (const float*)d_in[0];
    const float* rw = (const float*)d_in[1];
    const float* rb = (const float*)d_in[2];
    const float* wu = (const float*)d_in[3];
    const float* bu = (const float*)d_in[4];
    const float* wd = (const float*)d_in[5];
    const float* bd = (const float*)d_in[6];

    float* out       = (float*)d_out;
    float* out_y     = out;
    float* out_aux   = out + (size_t)NTOK * DIM;
    float* out_probs = out_aux + 1;

    cudaFuncSetAttribute(mma_gemm_kernel<true>,
        cudaFuncAttributeMaxDynamicSharedMemorySize, SMEM_BYTES);
    cudaFuncSetAttribute(mma_gemm_kernel<false>,
        cudaFuncAttributeMaxDynamicSharedMemorySize, SMEM_BYTES);

    __half* d_wuh = nullptr; cudaGetSymbolAddress((void**)&d_wuh, g_wuh);
    __half* d_wdh = nullptr; cudaGetSymbolAddress((void**)&d_wdh, g_wdh);

    // side stream for weight conversion, forked/joined via events (capture-safe)
    cudaStream_t s_side;
    cudaEvent_t ev_fork, ev_wu, ev_wd;
    cudaStreamCreateWithFlags(&s_side, cudaStreamNonBlocking);
    cudaEventCreateWithFlags(&ev_fork, cudaEventDisableTiming);
    cudaEventCreateWithFlags(&ev_wu, cudaEventDisableTiming);
    cudaEventCreateWithFlags(&ev_wd, cudaEventDisableTiming);

    zero_kernel<<<1, 32>>>();                                             // 1 (main)

    // fork: side stream converts w_up (|| router) then w_down (|| up-GEMM)
    cudaEventRecord(ev_fork, 0);
    cudaStreamWaitEvent(s_side, ev_fork, 0);
    cvt_w1_kernel<<<2368, 256, 0, s_side>>>((const float4*)wu, (uint2*)d_wuh);  // 2 (side)
    cudaEventRecord(ev_wu, s_side);

    router_kernel<<<NTOK, 256>>>(x, rw, rb, out_probs, out_y);            // 3 (main)

    cudaStreamWaitEvent(0, ev_wu, 0);   // up needs g_wuh
    dim3 gu(HID / TN, CAP / TM, NE);
    mma_gemm_kernel<true><<<gu, 256, SMEM_BYTES>>>(bu, out_y);            // 4 (main) <- profiled

    cvt_w1_kernel<<<2368, 256, 0, s_side>>>((const float4*)wd, (uint2*)d_wdh);  // 5 (side, runs || up)
    cudaEventRecord(ev_wd, s_side);

    aux_kernel<<<1, 32>>>(out_aux);                                       // 6 (main)

    cudaStreamWaitEvent(0, ev_wd, 0);   // down needs g_wdh (join side stream)
    dim3 gd(DIM / TN, CAP / TM, NE);
    mma_gemm_kernel<false><<<gd, 256, SMEM_BYTES>>>(bd, out_y);           // 7 (main)
}